// round 16
// baseline (speedup 1.0000x reference)
#include <cuda_runtime.h>
#include <cuda_bf16.h>
#include <math.h>
#include <stdint.h>

// ---------------- problem constants ----------------
#define CB0   8
#define CCIN  3
#define CGH   17
#define CGW   90
#define CPH   20
#define CPW   8
#define CHID  128
#define CNL   4
#define CNH   4
#define CHD   64
#define CDIN  256
#define CCONVD 512
#define CPROJ 772
#define CL    1530
#define CBZ   16
#define CPATCH 480
#define CEPS  1e-5f

#define M_FWD  (CB0*CL)
#define M_ALL  (CBZ*CL)

#define SCHUNK 18
#define SNCH   (CL / SCHUNK)   // 85

#define GKS 36                        // GEMM SMEM row stride (words)
#define GSM_W_OFF (2*128*GKS)         // Ws offset (words)
#define GSMEM_B   ((2*128*GKS + 2*64*GKS)*4)   // 55296 bytes dynamic

// ---------------- scratch ----------------
__device__ float g_h   [CBZ*CL*CHID];
__device__ float g_u   [CBZ*CL*CHID];
__device__ float g_proj[CBZ*CL*CPROJ];
__device__ float g_xc  [CBZ*CL*CCONVD];
__device__ float g_dt  [CBZ*CL*CNH];
__device__ float g_dA  [CBZ*CL*CNH];
__device__ float g_y   [CBZ*CL*CDIN];
__device__ float g_g   [CBZ*CL*CDIN];
__device__ float g_m   [CB0*CL*CHID];

// ---------------- tf32 / f32x2 helpers ----------------
__device__ __forceinline__ uint32_t f2tf32(float f) {
    uint32_t u;
    asm("cvt.rna.tf32.f32 %0, %1;" : "=r"(u) : "f"(f));
    return u;
}
__device__ __forceinline__ void mma_tf32(float* c, uint32_t a0, uint32_t a1,
                                         uint32_t a2, uint32_t a3,
                                         uint32_t b0, uint32_t b1) {
    asm volatile(
        "mma.sync.aligned.m16n8k8.row.col.f32.tf32.tf32.f32 "
        "{%0,%1,%2,%3},{%4,%5,%6,%7},{%8,%9},{%0,%1,%2,%3};"
        : "+f"(c[0]), "+f"(c[1]), "+f"(c[2]), "+f"(c[3])
        : "r"(a0), "r"(a1), "r"(a2), "r"(a3), "r"(b0), "r"(b1));
}
__device__ __forceinline__ unsigned long long fma_x2(unsigned long long a,
                                                     unsigned long long b,
                                                     unsigned long long c) {
    unsigned long long d;
    asm("fma.rn.f32x2 %0, %1, %2, %3;" : "=l"(d) : "l"(a), "l"(b), "l"(c));
    return d;
}
__device__ __forceinline__ unsigned long long mul_x2(unsigned long long a,
                                                     unsigned long long b) {
    unsigned long long d;
    asm("mul.rn.f32x2 %0, %1, %2;" : "=l"(d) : "l"(a), "l"(b));
    return d;
}
__device__ __forceinline__ unsigned long long add_x2(unsigned long long a,
                                                     unsigned long long b) {
    unsigned long long d;
    asm("add.rn.f32x2 %0, %1, %2;" : "=l"(d) : "l"(a), "l"(b));
    return d;
}
__device__ __forceinline__ unsigned long long pack2(float v) {
    unsigned long long d;
    asm("mov.b64 %0, {%1, %1};" : "=l"(d) : "r"(__float_as_uint(v)));
    return d;
}
__device__ __forceinline__ float unpack_sum(unsigned long long v) {
    uint32_t lo, hi;
    asm("mov.b64 {%0, %1}, %2;" : "=r"(lo), "=r"(hi) : "l"(v));
    return __uint_as_float(lo) + __uint_as_float(hi);
}

// ---------------- tensor-core GEMM (R13 proven: cp.async, convert-at-consume, 64x16 warp tile)
// MODE 0: +bias. MODE 1: +bias+residual. MODE 2: +bias+GELU.
// MODE 3: A gathered from image (patch embed). MODE 4: unpatchify scatter epilogue.
template<int MODE>
__device__ __forceinline__ const float* gemm_src_a(const float* __restrict__ A,
                                                   int gr, int col, int K) {
    if (MODE == 3) {
        int b = gr / CL, l = gr % CL;
        int i = l / CGW, j = l % CGW;
        int cc = col / 160, rem = col % 160;
        int p = rem >> 3, q = rem & 7;
        return A + (((size_t)(b * CCIN + cc) * 340) + i * CPH + p) * 720 + j * CPW + q;
    }
    return A + (size_t)gr * K + col;
}

template<int MODE>
__global__ void __launch_bounds__(256, 3)
gemm_tc(const float* __restrict__ A, const float* __restrict__ W,
        const float* __restrict__ bias, const float* __restrict__ R,
        float* __restrict__ C, int M, int N, int K)
{
    extern __shared__ float gsm[];   // [2][128][GKS] A, then [2][64][GKS] W

    const int tid  = threadIdx.x;
    const int warp = tid >> 5;
    const int lane = tid & 31;
    const int g    = lane >> 2;
    const int t    = lane & 3;
    const int wm   = warp >> 2;
    const int wn   = warp & 3;
    const int row0 = blockIdx.y * 128;
    const int col0 = blockIdx.x * 64;

    float acc[4][2][4];
#pragma unroll
    for (int mt = 0; mt < 4; mt++)
#pragma unroll
        for (int nt = 0; nt < 2; nt++)
#pragma unroll
            for (int j = 0; j < 4; j++) acc[mt][nt][j] = 0.f;

#define G_ISSUE(buf_, k0_)                                                              \
    {                                                                                   \
        _Pragma("unroll")                                                               \
        for (int u = 0; u < 4; u++) {                                                   \
            int i = tid + u * 256;                                                      \
            int r = i >> 3, c4 = (i & 7) << 2;                                          \
            int gr = row0 + r;                                                          \
            if (gr < M) {                                                               \
                uint32_t da = (uint32_t)__cvta_generic_to_shared(                       \
                    gsm + (buf_) * 128 * GKS + r * GKS + c4);                           \
                const float* src = gemm_src_a<MODE>(A, gr, (k0_) + c4, K);              \
                asm volatile("cp.async.ca.shared.global [%0], [%1], 16;"                \
                             :: "r"(da), "l"(src));                                     \
            }                                                                           \
        }                                                                               \
        _Pragma("unroll")                                                               \
        for (int u = 0; u < 2; u++) {                                                   \
            int i = tid + u * 256;                                                      \
            int r = i >> 3, c4 = (i & 7) << 2;                                          \
            int gc = col0 + r;                                                          \
            if (gc < N) {                                                               \
                uint32_t da = (uint32_t)__cvta_generic_to_shared(                       \
                    gsm + GSM_W_OFF + (buf_) * 64 * GKS + r * GKS + c4);                \
                const float* src = W + (size_t)gc * K + (k0_) + c4;                     \
                asm volatile("cp.async.ca.shared.global [%0], [%1], 16;"                \
                             :: "r"(da), "l"(src));                                     \
            }                                                                           \
        }                                                                               \
        asm volatile("cp.async.commit_group;");                                         \
    }

    const int ktiles = K >> 5;
    G_ISSUE(0, 0);
    if (ktiles > 1) G_ISSUE(1, 32);

    for (int kt = 0; kt < ktiles; kt++) {
        if (kt + 1 < ktiles) { asm volatile("cp.async.wait_group 1;"); }
        else                 { asm volatile("cp.async.wait_group 0;"); }
        __syncthreads();

        const float* Ab = gsm + (kt & 1) * 128 * GKS;
        const float* Wb = gsm + GSM_W_OFF + (kt & 1) * 64 * GKS;

#pragma unroll
        for (int ks = 0; ks < 4; ks++) {
            const int kb = ks << 3;
            uint32_t bfr[2][2];
#pragma unroll
            for (int nt = 0; nt < 2; nt++) {
                const float* wr = Wb + (wn * 16 + nt * 8 + g) * GKS + kb;
                bfr[nt][0] = f2tf32(wr[t]);
                bfr[nt][1] = f2tf32(wr[t + 4]);
            }
#pragma unroll
            for (int mt = 0; mt < 4; mt++) {
                const float* ar0 = Ab + (wm * 64 + mt * 16 + g) * GKS + kb;
                const float* ar1 = Ab + (wm * 64 + mt * 16 + g + 8) * GKS + kb;
                uint32_t a0 = f2tf32(ar0[t]);
                uint32_t a1 = f2tf32(ar1[t]);
                uint32_t a2 = f2tf32(ar0[t + 4]);
                uint32_t a3 = f2tf32(ar1[t + 4]);
#pragma unroll
                for (int nt = 0; nt < 2; nt++)
                    mma_tf32(acc[mt][nt], a0, a1, a2, a3, bfr[nt][0], bfr[nt][1]);
            }
        }
        __syncthreads();
        if (kt + 2 < ktiles) G_ISSUE(kt & 1, (kt + 2) << 5);
    }
#undef G_ISSUE

#pragma unroll
    for (int mt = 0; mt < 4; mt++) {
        int rl = row0 + wm * 64 + mt * 16 + g;
#pragma unroll
        for (int half = 0; half < 2; half++) {
            int r = rl + half * 8;
            if (r >= M) continue;
#pragma unroll
            for (int nt = 0; nt < 2; nt++) {
                int cb = col0 + wn * 16 + nt * 8 + 2 * t;
#pragma unroll
                for (int j = 0; j < 2; j++) {
                    int c = cb + j;
                    if (c >= N) continue;
                    float v = acc[mt][nt][half * 2 + j] + bias[c];
                    if (MODE == 1) v += R[(size_t)r * N + c];
                    if (MODE == 2) v = 0.5f * v * (1.f + erff(v * 0.70710678118654752f));
                    if (MODE == 4) {
                        // r2 column order: col = (p*PW + q)*CIN + cin
                        int b_ = r / CL, l = r % CL;
                        int i = l / CGW, jj = l % CGW;
                        int cin = c % 3;
                        int pq  = c / 3;
                        int q   = pq & 7;
                        int p   = pq >> 3;
                        C[(((size_t)(b_ * CCIN + cin) * 340) + i * CPH + p) * 720
                          + jj * CPW + q] = v;
                    } else {
                        C[(size_t)r * N + c] = v;
                    }
                }
            }
        }
    }
}

// ---------------- build h ----------------
__global__ void build_h(const float* __restrict__ seq, float* __restrict__ h)
{
    int idx = blockIdx.x * blockDim.x + threadIdx.x;
    if (idx >= CB0 * CL * CHID) return;
    int d = idx & 127;
    int l = (idx >> 7) % CL;
    int b = idx / (CL * CHID);
    float v;
    if (d < 127) v = seq[(size_t)(b * CL + l) * 127 + d];
    else         v = (float)(l / CGW) * (1.f / 16.f);
    h[idx] = v;
    h[(size_t)(CB0 + b) * CL * CHID + (size_t)(CL - 1 - l) * CHID + d] = v;
}

// ---------------- RMSNorm over 128 (warp per row) ----------------
__global__ void rmsnorm_kernel(const float* __restrict__ in, const float* __restrict__ w,
                               float* __restrict__ out, int rows)
{
    int warp = blockIdx.x * (blockDim.x >> 5) + (threadIdx.x >> 5);
    if (warp >= rows) return;
    int lane = threadIdx.x & 31;
    float4 v = reinterpret_cast<const float4*>(in + (size_t)warp * CHID)[lane];
    float ss = v.x * v.x + v.y * v.y + v.z * v.z + v.w * v.w;
#pragma unroll
    for (int o = 16; o; o >>= 1) ss += __shfl_xor_sync(0xffffffffu, ss, o);
    float sc = rsqrtf(ss * (1.f / 128.f) + CEPS);
    float4 wv = reinterpret_cast<const float4*>(w)[lane];
    float4 ov = make_float4(v.x * sc * wv.x, v.y * sc * wv.y, v.z * sc * wv.z, v.w * sc * wv.w);
    reinterpret_cast<float4*>(out + (size_t)warp * CHID)[lane] = ov;
}

// ---------------- depthwise causal conv(K=4) + SiLU, float4 per thread ----------------
__global__ void conv_kernel(const float* __restrict__ proj, const float* __restrict__ cw,
                            const float* __restrict__ cb, float* __restrict__ xc)
{
    int idx = blockIdx.x * blockDim.x + threadIdx.x;
    if (idx >= CBZ * CL * (CCONVD / 4)) return;
    int c4 = (idx & 127) << 2;
    int l  = (idx >> 7) % CL;
    int b  = idx / (128 * CL);
    const float* pr = proj + (size_t)(b * CL) * CPROJ + CDIN + c4;
    float4 w0 = reinterpret_cast<const float4*>(cw)[c4 + 0];
    float4 w1 = reinterpret_cast<const float4*>(cw)[c4 + 1];
    float4 w2 = reinterpret_cast<const float4*>(cw)[c4 + 2];
    float4 w3 = reinterpret_cast<const float4*>(cw)[c4 + 3];
    float4 s = reinterpret_cast<const float4*>(cb)[c4 >> 2];
#pragma unroll
    for (int k = 0; k < 4; k++) {
        int ls = l - 3 + k;
        if (ls >= 0) {
            float4 v = *reinterpret_cast<const float4*>(&pr[(size_t)ls * CPROJ]);
            float tw0 = (&w0.x)[k], tw1 = (&w1.x)[k], tw2 = (&w2.x)[k], tw3 = (&w3.x)[k];
            s.x += tw0 * v.x; s.y += tw1 * v.y; s.z += tw2 * v.z; s.w += tw3 * v.w;
        }
    }
    s.x = s.x / (1.f + __expf(-s.x));
    s.y = s.y / (1.f + __expf(-s.y));
    s.z = s.z / (1.f + __expf(-s.z));
    s.w = s.w / (1.f + __expf(-s.w));
    reinterpret_cast<float4*>(xc)[idx] = s;
}

// ---------------- dt prep ----------------
__global__ void dtprep_kernel(const float* __restrict__ proj, const float* __restrict__ dtb,
                              const float* __restrict__ alog, float* __restrict__ dt,
                              float* __restrict__ dA)
{
    int idx = blockIdx.x * blockDim.x + threadIdx.x;
    if (idx >= CBZ * CL * CNH) return;
    int h = idx & 3;
    int token = idx >> 2;
    float xv = proj[(size_t)token * CPROJ + (CDIN + CCONVD) + h] + dtb[h];
    float sp = (xv > 20.f) ? xv : log1pf(__expf(xv));
    dt[idx] = sp;
    dA[idx] = __expf(-__expf(alog[h]) * sp);
}

// ---------------- SSM scan v4: 4-way p split -> 256 CTAs, 2/SM ----------------
// grid (4, 4, 16) = (pg, h, b), 256 threads = 16 p x 16 noct (8 n each).
__global__ void __launch_bounds__(256)
scan_kernel(const float* __restrict__ xc, const float* __restrict__ dt,
            const float* __restrict__ dA, float* __restrict__ y)
{
    const int pg = blockIdx.x;           // 0..3 : p quarter (16 p each)
    const int h  = blockIdx.y;
    const int b  = blockIdx.z;
    const int tid = threadIdx.x;
    const int p_local = tid >> 4;        // 0..15
    const int noct    = tid & 15;        // 0..15
    const int nb      = noct << 3;       // n base (8 n's per thread)

    __shared__ __align__(16) float sBC[2][SCHUNK][288];
    __shared__ __align__(16) float sX [2][SCHUNK][16];
    __shared__ float sDT[2][SCHUNK];
    __shared__ float sDA[2][SCHUNK];

    const float* xcb = xc + (size_t)b * CL * CCONVD;
    const float* dtb = dt + ((size_t)b * CL) * CNH + h;
    const float* dAb = dA + ((size_t)b * CL) * CNH + h;
    float* yb = y + (size_t)b * CL * CDIN + h * CHD + pg * 16;
    const int xoff = h * CHD + pg * 16;

    unsigned long long s2[4];
#pragma unroll
    for (int i = 0; i < 4; i++) s2[i] = 0ull;

    const int gB = ((nb >> 5) * 36) + (nb & 31);
    const int gC = (((nb + 128) >> 5) * 36) + ((nb + 128) & 31);

#define SCAN_ISSUE(cc)                                                              \
    {                                                                               \
        const int buf_ = (cc) & 1;                                                  \
        const int t0_  = (cc) * SCHUNK;                                             \
        for (int i = tid; i < SCHUNK * 64; i += 256) {                              \
            int tt = i >> 6, n0 = (i & 63) << 2;                                    \
            int doff = ((n0 >> 5) * 36) + (n0 & 31);                                \
            uint32_t da = (uint32_t)__cvta_generic_to_shared(&sBC[buf_][tt][doff]); \
            const float* src = xcb + (size_t)(t0_ + tt) * CCONVD + CDIN + n0;       \
            asm volatile("cp.async.ca.shared.global [%0], [%1], 16;" :: "r"(da), "l"(src)); \
        }                                                                           \
        if (tid < SCHUNK * 4) {                                                     \
            int tt = tid >> 2, n0 = (tid & 3) << 2;                                 \
            uint32_t da = (uint32_t)__cvta_generic_to_shared(&sX[buf_][tt][n0]);    \
            const float* src = xcb + (size_t)(t0_ + tt) * CCONVD + xoff + n0;       \
            asm volatile("cp.async.ca.shared.global [%0], [%1], 16;" :: "r"(da), "l"(src)); \
        }                                                                           \
        if (tid < SCHUNK) {                                                         \
            uint32_t da = (uint32_t)__cvta_generic_to_shared(&sDT[buf_][tid]);      \
            const float* src = dtb + (size_t)(t0_ + tid) * CNH;                     \
            asm volatile("cp.async.ca.shared.global [%0], [%1], 4;" :: "r"(da), "l"(src)); \
            uint32_t da2 = (uint32_t)__cvta_generic_to_shared(&sDA[buf_][tid]);     \
            const float* src2 = dAb + (size_t)(t0_ + tid) * CNH;                    \
            asm volatile("cp.async.ca.shared.global [%0], [%1], 4;" :: "r"(da2), "l"(src2)); \
        }                                                                           \
        asm volatile("cp.async.commit_group;");                                     \
    }

    SCAN_ISSUE(0);

    for (int c = 0; c < SNCH; c++) {
        asm volatile("cp.async.wait_group 0;");
        __syncthreads();
        if (c + 1 < SNCH) SCAN_ISSUE(c + 1);
        const int buf = c & 1;
        const int t0 = c * SCHUNK;
#pragma unroll 6
        for (int tt = 0; tt < SCHUNK; tt++) {
            const unsigned long long a2  = pack2(sDA[buf][tt]);
            const unsigned long long sc2 = pack2(sDT[buf][tt] * sX[buf][tt][p_local]);
            const float* base = &sBC[buf][tt][0];
            unsigned long long accA = 0ull, accB = 0ull;
#pragma unroll
            for (int q = 0; q < 2; q++) {
                ulonglong2 bq = *reinterpret_cast<const ulonglong2*>(base + gB + 4 * q);
                ulonglong2 cq = *reinterpret_cast<const ulonglong2*>(base + gC + 4 * q);
                s2[2*q]   = fma_x2(a2, s2[2*q],   mul_x2(sc2, bq.x));
                s2[2*q+1] = fma_x2(a2, s2[2*q+1], mul_x2(sc2, bq.y));
                accA = fma_x2(s2[2*q],   cq.x, accA);
                accB = fma_x2(s2[2*q+1], cq.y, accB);
            }
            float acc = unpack_sum(add_x2(accA, accB));
            acc += __shfl_xor_sync(0xffffffffu, acc, 1);
            acc += __shfl_xor_sync(0xffffffffu, acc, 2);
            acc += __shfl_xor_sync(0xffffffffu, acc, 4);
            acc += __shfl_xor_sync(0xffffffffu, acc, 8);
            if (noct == 0) yb[(size_t)(t0 + tt) * CDIN + p_local] = acc;
        }
    }
#undef SCAN_ISSUE
}

// ---------------- gate+norm: warp per token ----------------
__global__ void gate_norm_kernel(const float* __restrict__ y, const float* __restrict__ xc,
                                 const float* __restrict__ proj, const float* __restrict__ Dv,
                                 const float* __restrict__ gw, float* __restrict__ out)
{
    int token = blockIdx.x * 8 + (threadIdx.x >> 5);
    int lane = threadIdx.x & 31;
    const float4* yrow = reinterpret_cast<const float4*>(y + (size_t)token * CDIN);
    const float4* xrow = reinterpret_cast<const float4*>(xc + (size_t)token * CCONVD);
    const float4* zrow = reinterpret_cast<const float4*>(proj + (size_t)token * CPROJ);
    float4 ya = yrow[lane],      yb2 = yrow[lane + 32];
    float4 xa = xrow[lane],      xb  = xrow[lane + 32];
    float4 za = zrow[lane],      zb  = zrow[lane + 32];
    float Da = Dv[lane >> 4];
    float Db = Dv[2 + (lane >> 4)];

    float4 va, vb;
    va.x = (ya.x + Da * xa.x) * (za.x / (1.f + __expf(-za.x)));
    va.y = (ya.y + Da * xa.y) * (za.y / (1.f + __expf(-za.y)));
    va.z = (ya.z + Da * xa.z) * (za.z / (1.f + __expf(-za.z)));
    va.w = (ya.w + Da * xa.w) * (za.w / (1.f + __expf(-za.w)));
    vb.x = (yb2.x + Db * xb.x) * (zb.x / (1.f + __expf(-zb.x)));
    vb.y = (yb2.y + Db * xb.y) * (zb.y / (1.f + __expf(-zb.y)));
    vb.z = (yb2.z + Db * xb.z) * (zb.z / (1.f + __expf(-zb.z)));
    vb.w = (yb2.w + Db * xb.w) * (zb.w / (1.f + __expf(-zb.w)));

    float ss = va.x*va.x + va.y*va.y + va.z*va.z + va.w*va.w
             + vb.x*vb.x + vb.y*vb.y + vb.z*vb.z + vb.w*vb.w;
#pragma unroll
    for (int o = 16; o; o >>= 1) ss += __shfl_xor_sync(0xffffffffu, ss, o);
    float sc = rsqrtf(ss * (1.f / 256.f) + CEPS);

    float4 ga = reinterpret_cast<const float4*>(gw)[lane];
    float4 gb = reinterpret_cast<const float4*>(gw)[lane + 32];
    float4 oa = make_float4(va.x*sc*ga.x, va.y*sc*ga.y, va.z*sc*ga.z, va.w*sc*ga.w);
    float4 ob = make_float4(vb.x*sc*gb.x, vb.y*sc*gb.y, vb.z*sc*gb.z, vb.w*sc*gb.w);
    float4* orow = reinterpret_cast<float4*>(out + (size_t)token * CDIN);
    orow[lane] = oa;
    orow[lane + 32] = ob;
}

// ---------------- head: fnorm RMSNorm + fwd/bwd merge, warp per token ----------------
__global__ void fnorm_merge_kernel(const float* __restrict__ h, const float* __restrict__ w,
                                   float* __restrict__ m)
{
    int tok = blockIdx.x * 8 + (threadIdx.x >> 5);
    int lane = threadIdx.x & 31;
    int b = tok / CL, l = tok % CL;
    const float4* rf = reinterpret_cast<const float4*>(h + (size_t)tok * CHID);
    const float4* rb = reinterpret_cast<const float4*>(
        h + (size_t)((CB0 + b) * CL + (CL - 1 - l)) * CHID);
    float4 a = rf[lane], c = rb[lane];
    float sa = a.x*a.x + a.y*a.y + a.z*a.z + a.w*a.w;
    float sb = c.x*c.x + c.y*c.y + c.z*c.z + c.w*c.w;
#pragma unroll
    for (int o = 16; o; o >>= 1) {
        sa += __shfl_xor_sync(0xffffffffu, sa, o);
        sb += __shfl_xor_sync(0xffffffffu, sb, o);
    }
    float ka = rsqrtf(sa * (1.f / 128.f) + CEPS);
    float kb = rsqrtf(sb * (1.f / 128.f) + CEPS);
    float4 wv = reinterpret_cast<const float4*>(w)[lane];
    float4 o4 = make_float4(0.5f * (a.x * ka + c.x * kb) * wv.x,
                            0.5f * (a.y * ka + c.y * kb) * wv.y,
                            0.5f * (a.z * ka + c.z * kb) * wv.z,
                            0.5f * (a.w * ka + c.w * kb) * wv.w);
    reinterpret_cast<float4*>(m + (size_t)tok * CHID)[lane] = o4;
}

// ---------------- launcher ----------------
extern "C" void kernel_launch(void* const* d_in, const int* in_sizes, int n_in,
                              void* d_out, int out_size)
{
    const float* x        = (const float*)d_in[0];
    const float* patch_w  = (const float*)d_in[1];
    const float* patch_b  = (const float*)d_in[2];
    const float* ln_w     = (const float*)d_in[3];
    const float* in_w     = (const float*)d_in[4];
    const float* in_b     = (const float*)d_in[5];
    const float* conv_w   = (const float*)d_in[6];
    const float* conv_b   = (const float*)d_in[7];
    const float* dt_bias  = (const float*)d_in[8];
    const float* A_log    = (const float*)d_in[9];
    const float* Dw       = (const float*)d_in[10];
    const float* gnorm_w  = (const float*)d_in[11];
    const float* out_w    = (const float*)d_in[12];
    const float* out_b    = (const float*)d_in[13];
    const float* fnorm_w  = (const float*)d_in[14];
    const float* r1_w     = (const float*)d_in[15];
    const float* r1_b     = (const float*)d_in[16];
    const float* r2_w     = (const float*)d_in[17];
    const float* r2_b     = (const float*)d_in[18];

    float *h_, *u_, *proj_, *xc_, *dt_, *dA_, *y_, *g_, *m_;
    cudaGetSymbolAddress((void**)&h_,    g_h);
    cudaGetSymbolAddress((void**)&u_,    g_u);
    cudaGetSymbolAddress((void**)&proj_, g_proj);
    cudaGetSymbolAddress((void**)&xc_,   g_xc);
    cudaGetSymbolAddress((void**)&dt_,   g_dt);
    cudaGetSymbolAddress((void**)&dA_,   g_dA);
    cudaGetSymbolAddress((void**)&y_,    g_y);
    cudaGetSymbolAddress((void**)&g_,    g_g);
    cudaGetSymbolAddress((void**)&m_,    g_m);

    // Idempotent dynamic-SMEM attribute (no static guards).
    cudaFuncSetAttribute(gemm_tc<0>, cudaFuncAttributeMaxDynamicSharedMemorySize, GSMEM_B);
    cudaFuncSetAttribute(gemm_tc<1>, cudaFuncAttributeMaxDynamicSharedMemorySize, GSMEM_B);
    cudaFuncSetAttribute(gemm_tc<2>, cudaFuncAttributeMaxDynamicSharedMemorySize, GSMEM_B);
    cudaFuncSetAttribute(gemm_tc<3>, cudaFuncAttributeMaxDynamicSharedMemorySize, GSMEM_B);
    cudaFuncSetAttribute(gemm_tc<4>, cudaFuncAttributeMaxDynamicSharedMemorySize, GSMEM_B);

    // 1. patch embedding (gather fused into GEMM A-load)
    gemm_tc<3><<<dim3(2, 96), 256, GSMEM_B>>>(x, patch_w, patch_b, nullptr, y_,
                                              M_FWD, 127, CPATCH);
    build_h<<<(CB0 * CL * CHID + 255) / 256, 256>>>(y_, h_);

    // 2. mixer layers
    for (int layer = 0; layer < CNL; layer++) {
        rmsnorm_kernel<<<M_ALL / 8, 256>>>(h_, ln_w + layer * CHID, u_, M_ALL);
        gemm_tc<0><<<dim3(13, 192), 256, GSMEM_B>>>(u_, in_w + (size_t)layer * CPROJ * CHID,
                                                    in_b + layer * CPROJ, nullptr, proj_,
                                                    M_ALL, CPROJ, CHID);
        conv_kernel<<<(CBZ * CL * 128 + 255) / 256, 256>>>(
            proj_, conv_w + (size_t)layer * CCONVD * 4, conv_b + layer * CCONVD, xc_);
        dtprep_kernel<<<(CBZ * CL * CNH + 255) / 256, 256>>>(
            proj_, dt_bias + layer * CNH, A_log + layer * CNH, dt_, dA_);
        scan_kernel<<<dim3(4, CNH, CBZ), 256>>>(xc_, dt_, dA_, y_);
        gate_norm_kernel<<<M_ALL / 8, 256>>>(y_, xc_, proj_, Dw + layer * CNH,
                                             gnorm_w + layer * CDIN, g_);
        gemm_tc<1><<<dim3(2, 192), 256, GSMEM_B>>>(g_, out_w + (size_t)layer * CHID * CDIN,
                                                   out_b + layer * CHID, h_, h_,
                                                   M_ALL, CHID, CDIN);
    }

    // 3. head: fused fnorm+merge, r1 (GELU), r2 with unpatchify scatter epilogue
    fnorm_merge_kernel<<<M_FWD / 8, 256>>>(h_, fnorm_w, m_);
    gemm_tc<2><<<dim3(2, 96), 256, GSMEM_B>>>(m_, r1_w, r1_b, nullptr, u_, M_FWD, CHID, CHID);
    gemm_tc<4><<<dim3(8, 96), 256, GSMEM_B>>>(u_, r2_w, r2_b, nullptr, (float*)d_out,
                                              M_FWD, CPATCH, CHID);
}

// round 17
// speedup vs baseline: 1.2002x; 1.2002x over previous
#include <cuda_runtime.h>
#include <cuda_bf16.h>
#include <math.h>
#include <stdint.h>

// ---------------- problem constants ----------------
#define CB0   8
#define CCIN  3
#define CGH   17
#define CGW   90
#define CPH   20
#define CPW   8
#define CHID  128
#define CNL   4
#define CNH   4
#define CHD   64
#define CDIN  256
#define CCONVD 512
#define CPROJ 772
#define CL    1530
#define CBZ   16
#define CPATCH 480
#define CEPS  1e-5f

#define M_FWD  (CB0*CL)
#define M_ALL  (CBZ*CL)

#define SCHUNK 18
#define SNCH   (CL / SCHUNK)   // 85

#define GKS 36                        // GEMM SMEM row stride (words)
#define GSM_W_OFF (2*128*GKS)         // Ws offset (words)
#define GSMEM_B   ((2*128*GKS + 2*64*GKS)*4)   // 55296 bytes dynamic

// ---------------- scratch ----------------
__device__ float g_h   [CBZ*CL*CHID];
__device__ float g_u   [CBZ*CL*CHID];
__device__ float g_proj[CBZ*CL*CPROJ];
__device__ float g_xc  [CBZ*CL*CCONVD];
__device__ float g_dt  [CBZ*CL*CNH];
__device__ float g_dA  [CBZ*CL*CNH];
__device__ float g_y   [CBZ*CL*CDIN];
__device__ float g_g   [CBZ*CL*CDIN];
__device__ float g_m   [CB0*CL*CHID];

// ---------------- tf32 / f32x2 helpers ----------------
__device__ __forceinline__ uint32_t f2tf32(float f) {
    uint32_t u;
    asm("cvt.rna.tf32.f32 %0, %1;" : "=r"(u) : "f"(f));
    return u;
}
__device__ __forceinline__ void mma_tf32(float* c, uint32_t a0, uint32_t a1,
                                         uint32_t a2, uint32_t a3,
                                         uint32_t b0, uint32_t b1) {
    asm volatile(
        "mma.sync.aligned.m16n8k8.row.col.f32.tf32.tf32.f32 "
        "{%0,%1,%2,%3},{%4,%5,%6,%7},{%8,%9},{%0,%1,%2,%3};"
        : "+f"(c[0]), "+f"(c[1]), "+f"(c[2]), "+f"(c[3])
        : "r"(a0), "r"(a1), "r"(a2), "r"(a3), "r"(b0), "r"(b1));
}
__device__ __forceinline__ unsigned long long fma_x2(unsigned long long a,
                                                     unsigned long long b,
                                                     unsigned long long c) {
    unsigned long long d;
    asm("fma.rn.f32x2 %0, %1, %2, %3;" : "=l"(d) : "l"(a), "l"(b), "l"(c));
    return d;
}
__device__ __forceinline__ unsigned long long mul_x2(unsigned long long a,
                                                     unsigned long long b) {
    unsigned long long d;
    asm("mul.rn.f32x2 %0, %1, %2;" : "=l"(d) : "l"(a), "l"(b));
    return d;
}
__device__ __forceinline__ unsigned long long add_x2(unsigned long long a,
                                                     unsigned long long b) {
    unsigned long long d;
    asm("add.rn.f32x2 %0, %1, %2;" : "=l"(d) : "l"(a), "l"(b));
    return d;
}
__device__ __forceinline__ unsigned long long pack2(float v) {
    unsigned long long d;
    asm("mov.b64 %0, {%1, %1};" : "=l"(d) : "r"(__float_as_uint(v)));
    return d;
}
__device__ __forceinline__ float unpack_sum(unsigned long long v) {
    uint32_t lo, hi;
    asm("mov.b64 {%0, %1}, %2;" : "=r"(lo), "=r"(hi) : "l"(v));
    return __uint_as_float(lo) + __uint_as_float(hi);
}

// ---------------- tensor-core GEMM (R13 proven) ----------------
// MODE 0: +bias. MODE 1: +bias+residual. MODE 2: +bias+GELU.
// MODE 3: A gathered from image (patch embed). MODE 4: unpatchify scatter epilogue.
template<int MODE>
__device__ __forceinline__ const float* gemm_src_a(const float* __restrict__ A,
                                                   int gr, int col, int K) {
    if (MODE == 3) {
        int b = gr / CL, l = gr % CL;
        int i = l / CGW, j = l % CGW;
        int cc = col / 160, rem = col % 160;
        int p = rem >> 3, q = rem & 7;
        return A + (((size_t)(b * CCIN + cc) * 340) + i * CPH + p) * 720 + j * CPW + q;
    }
    return A + (size_t)gr * K + col;
}

template<int MODE>
__global__ void __launch_bounds__(256, 3)
gemm_tc(const float* __restrict__ A, const float* __restrict__ W,
        const float* __restrict__ bias, const float* __restrict__ R,
        float* __restrict__ C, int M, int N, int K)
{
    extern __shared__ float gsm[];   // [2][128][GKS] A, then [2][64][GKS] W

    const int tid  = threadIdx.x;
    const int warp = tid >> 5;
    const int lane = tid & 31;
    const int g    = lane >> 2;
    const int t    = lane & 3;
    const int wm   = warp >> 2;
    const int wn   = warp & 3;
    const int row0 = blockIdx.y * 128;
    const int col0 = blockIdx.x * 64;

    float acc[4][2][4];
#pragma unroll
    for (int mt = 0; mt < 4; mt++)
#pragma unroll
        for (int nt = 0; nt < 2; nt++)
#pragma unroll
            for (int j = 0; j < 4; j++) acc[mt][nt][j] = 0.f;

#define G_ISSUE(buf_, k0_)                                                              \
    {                                                                                   \
        _Pragma("unroll")                                                               \
        for (int u = 0; u < 4; u++) {                                                   \
            int i = tid + u * 256;                                                      \
            int r = i >> 3, c4 = (i & 7) << 2;                                          \
            int gr = row0 + r;                                                          \
            if (gr < M) {                                                               \
                uint32_t da = (uint32_t)__cvta_generic_to_shared(                       \
                    gsm + (buf_) * 128 * GKS + r * GKS + c4);                           \
                const float* src = gemm_src_a<MODE>(A, gr, (k0_) + c4, K);              \
                asm volatile("cp.async.ca.shared.global [%0], [%1], 16;"                \
                             :: "r"(da), "l"(src));                                     \
            }                                                                           \
        }                                                                               \
        _Pragma("unroll")                                                               \
        for (int u = 0; u < 2; u++) {                                                   \
            int i = tid + u * 256;                                                      \
            int r = i >> 3, c4 = (i & 7) << 2;                                          \
            int gc = col0 + r;                                                          \
            if (gc < N) {                                                               \
                uint32_t da = (uint32_t)__cvta_generic_to_shared(                       \
                    gsm + GSM_W_OFF + (buf_) * 64 * GKS + r * GKS + c4);                \
                const float* src = W + (size_t)gc * K + (k0_) + c4;                     \
                asm volatile("cp.async.ca.shared.global [%0], [%1], 16;"                \
                             :: "r"(da), "l"(src));                                     \
            }                                                                           \
        }                                                                               \
        asm volatile("cp.async.commit_group;");                                         \
    }

    const int ktiles = K >> 5;
    G_ISSUE(0, 0);
    if (ktiles > 1) G_ISSUE(1, 32);

    for (int kt = 0; kt < ktiles; kt++) {
        if (kt + 1 < ktiles) { asm volatile("cp.async.wait_group 1;"); }
        else                 { asm volatile("cp.async.wait_group 0;"); }
        __syncthreads();

        const float* Ab = gsm + (kt & 1) * 128 * GKS;
        const float* Wb = gsm + GSM_W_OFF + (kt & 1) * 64 * GKS;

#pragma unroll
        for (int ks = 0; ks < 4; ks++) {
            const int kb = ks << 3;
            uint32_t bfr[2][2];
#pragma unroll
            for (int nt = 0; nt < 2; nt++) {
                const float* wr = Wb + (wn * 16 + nt * 8 + g) * GKS + kb;
                bfr[nt][0] = f2tf32(wr[t]);
                bfr[nt][1] = f2tf32(wr[t + 4]);
            }
#pragma unroll
            for (int mt = 0; mt < 4; mt++) {
                const float* ar0 = Ab + (wm * 64 + mt * 16 + g) * GKS + kb;
                const float* ar1 = Ab + (wm * 64 + mt * 16 + g + 8) * GKS + kb;
                uint32_t a0 = f2tf32(ar0[t]);
                uint32_t a1 = f2tf32(ar1[t]);
                uint32_t a2 = f2tf32(ar0[t + 4]);
                uint32_t a3 = f2tf32(ar1[t + 4]);
#pragma unroll
                for (int nt = 0; nt < 2; nt++)
                    mma_tf32(acc[mt][nt], a0, a1, a2, a3, bfr[nt][0], bfr[nt][1]);
            }
        }
        __syncthreads();
        if (kt + 2 < ktiles) G_ISSUE(kt & 1, (kt + 2) << 5);
    }
#undef G_ISSUE

#pragma unroll
    for (int mt = 0; mt < 4; mt++) {
        int rl = row0 + wm * 64 + mt * 16 + g;
#pragma unroll
        for (int half = 0; half < 2; half++) {
            int r = rl + half * 8;
            if (r >= M) continue;
#pragma unroll
            for (int nt = 0; nt < 2; nt++) {
                int cb = col0 + wn * 16 + nt * 8 + 2 * t;
#pragma unroll
                for (int j = 0; j < 2; j++) {
                    int c = cb + j;
                    if (c >= N) continue;
                    float v = acc[mt][nt][half * 2 + j] + bias[c];
                    if (MODE == 1) v += R[(size_t)r * N + c];
                    if (MODE == 2) v = 0.5f * v * (1.f + erff(v * 0.70710678118654752f));
                    if (MODE == 4) {
                        // r2 column order: col = (p*PW + q)*CIN + cin
                        int b_ = r / CL, l = r % CL;
                        int i = l / CGW, jj = l % CGW;
                        int cin = c % 3;
                        int pq  = c / 3;
                        int q   = pq & 7;
                        int p   = pq >> 3;
                        C[(((size_t)(b_ * CCIN + cin) * 340) + i * CPH + p) * 720
                          + jj * CPW + q] = v;
                    } else {
                        C[(size_t)r * N + c] = v;
                    }
                }
            }
        }
    }
}

// ---------------- build h ----------------
__global__ void build_h(const float* __restrict__ seq, float* __restrict__ h)
{
    int idx = blockIdx.x * blockDim.x + threadIdx.x;
    if (idx >= CB0 * CL * CHID) return;
    int d = idx & 127;
    int l = (idx >> 7) % CL;
    int b = idx / (CL * CHID);
    float v;
    if (d < 127) v = seq[(size_t)(b * CL + l) * 127 + d];
    else         v = (float)(l / CGW) * (1.f / 16.f);
    h[idx] = v;
    h[(size_t)(CB0 + b) * CL * CHID + (size_t)(CL - 1 - l) * CHID + d] = v;
}

// ---------------- RMSNorm over 128 (warp per row) ----------------
__global__ void rmsnorm_kernel(const float* __restrict__ in, const float* __restrict__ w,
                               float* __restrict__ out, int rows)
{
    int warp = blockIdx.x * (blockDim.x >> 5) + (threadIdx.x >> 5);
    if (warp >= rows) return;
    int lane = threadIdx.x & 31;
    float4 v = reinterpret_cast<const float4*>(in + (size_t)warp * CHID)[lane];
    float ss = v.x * v.x + v.y * v.y + v.z * v.z + v.w * v.w;
#pragma unroll
    for (int o = 16; o; o >>= 1) ss += __shfl_xor_sync(0xffffffffu, ss, o);
    float sc = rsqrtf(ss * (1.f / 128.f) + CEPS);
    float4 wv = reinterpret_cast<const float4*>(w)[lane];
    float4 ov = make_float4(v.x * sc * wv.x, v.y * sc * wv.y, v.z * sc * wv.z, v.w * sc * wv.w);
    reinterpret_cast<float4*>(out + (size_t)warp * CHID)[lane] = ov;
}

// ---------------- depthwise causal conv(K=4) + SiLU, sliding window (6 tokens/thread) --
__global__ void conv_kernel(const float* __restrict__ proj, const float* __restrict__ cw,
                            const float* __restrict__ cb, float* __restrict__ xc)
{
    int idx = blockIdx.x * blockDim.x + threadIdx.x;
    if (idx >= CBZ * 255 * 128) return;
    int c4 = (idx & 127) << 2;            // channel base (0,4,...,508)
    int t6 = (idx >> 7) % 255;
    int b  = idx / (128 * 255);
    int l0 = t6 * 6;
    const float* pr = proj + (size_t)(b * CL) * CPROJ + CDIN + c4;
    float4 w0 = reinterpret_cast<const float4*>(cw)[c4 + 0];
    float4 w1 = reinterpret_cast<const float4*>(cw)[c4 + 1];
    float4 w2 = reinterpret_cast<const float4*>(cw)[c4 + 2];
    float4 w3 = reinterpret_cast<const float4*>(cw)[c4 + 3];
    float4 bias4 = reinterpret_cast<const float4*>(cb)[c4 >> 2];

    float4 r[9];
#pragma unroll
    for (int i = 0; i < 9; i++) {
        int ls = l0 - 3 + i;      // l0+5 <= 1529 < CL always
        if (ls >= 0) r[i] = *reinterpret_cast<const float4*>(&pr[(size_t)ls * CPROJ]);
        else         r[i] = make_float4(0.f, 0.f, 0.f, 0.f);
    }
#pragma unroll
    for (int j = 0; j < 6; j++) {
        float4 s = bias4;
#pragma unroll
        for (int k = 0; k < 4; k++) {
            float4 v = r[j + k];
            s.x += (&w0.x)[k] * v.x;
            s.y += (&w1.x)[k] * v.y;
            s.z += (&w2.x)[k] * v.z;
            s.w += (&w3.x)[k] * v.w;
        }
        s.x = s.x / (1.f + __expf(-s.x));
        s.y = s.y / (1.f + __expf(-s.y));
        s.z = s.z / (1.f + __expf(-s.z));
        s.w = s.w / (1.f + __expf(-s.w));
        *reinterpret_cast<float4*>(&xc[((size_t)(b * CL + l0 + j)) * CCONVD + c4]) = s;
    }
}

// ---------------- dt prep ----------------
__global__ void dtprep_kernel(const float* __restrict__ proj, const float* __restrict__ dtb,
                              const float* __restrict__ alog, float* __restrict__ dt,
                              float* __restrict__ dA)
{
    int idx = blockIdx.x * blockDim.x + threadIdx.x;
    if (idx >= CBZ * CL * CNH) return;
    int h = idx & 3;
    int token = idx >> 2;
    float xv = proj[(size_t)token * CPROJ + (CDIN + CCONVD) + h] + dtb[h];
    float sp = (xv > 20.f) ? xv : log1pf(__expf(xv));
    dt[idx] = sp;
    dA[idx] = __expf(-__expf(alog[h]) * sp);
}

// ---------------- SSM scan (R6/R13 proven): chunked cp.async + f32x2 ----------------
__global__ void __launch_bounds__(256)
scan_kernel(const float* __restrict__ xc, const float* __restrict__ dt,
            const float* __restrict__ dA, float* __restrict__ y)
{
    const int pg = blockIdx.x;
    const int h  = blockIdx.y;
    const int b  = blockIdx.z;
    const int tid = threadIdx.x;
    const int p_local = tid >> 3;
    const int noct    = tid & 7;
    const int nb      = noct << 4;

    __shared__ __align__(16) float sBC[2][SCHUNK][288];
    __shared__ __align__(16) float sX [2][SCHUNK][32];
    __shared__ float sDT[2][SCHUNK];
    __shared__ float sDA[2][SCHUNK];

    const float* xcb = xc + (size_t)b * CL * CCONVD;
    const float* dtb = dt + ((size_t)b * CL) * CNH + h;
    const float* dAb = dA + ((size_t)b * CL) * CNH + h;
    float* yb = y + (size_t)b * CL * CDIN + h * CHD + pg * 32;
    const int xoff = h * CHD + pg * 32;

    unsigned long long s2[8];
#pragma unroll
    for (int i = 0; i < 8; i++) s2[i] = 0ull;

    const int gB = ((nb >> 5) * 36) + (nb & 31);
    const int gC = (((nb + 128) >> 5) * 36) + ((nb + 128) & 31);

#define SCAN_ISSUE(cc)                                                              \
    {                                                                               \
        const int buf_ = (cc) & 1;                                                  \
        const int t0_  = (cc) * SCHUNK;                                             \
        for (int i = tid; i < SCHUNK * 64; i += 256) {                              \
            int tt = i >> 6, n0 = (i & 63) << 2;                                    \
            int doff = ((n0 >> 5) * 36) + (n0 & 31);                                \
            uint32_t da = (uint32_t)__cvta_generic_to_shared(&sBC[buf_][tt][doff]); \
            const float* src = xcb + (size_t)(t0_ + tt) * CCONVD + CDIN + n0;       \
            asm volatile("cp.async.ca.shared.global [%0], [%1], 16;" :: "r"(da), "l"(src)); \
        }                                                                           \
        for (int i = tid; i < SCHUNK * 8; i += 256) {                               \
            int tt = i >> 3, n0 = (i & 7) << 2;                                     \
            uint32_t da = (uint32_t)__cvta_generic_to_shared(&sX[buf_][tt][n0]);    \
            const float* src = xcb + (size_t)(t0_ + tt) * CCONVD + xoff + n0;       \
            asm volatile("cp.async.ca.shared.global [%0], [%1], 16;" :: "r"(da), "l"(src)); \
        }                                                                           \
        if (tid < SCHUNK) {                                                         \
            uint32_t da = (uint32_t)__cvta_generic_to_shared(&sDT[buf_][tid]);      \
            const float* src = dtb + (size_t)(t0_ + tid) * CNH;                     \
            asm volatile("cp.async.ca.shared.global [%0], [%1], 4;" :: "r"(da), "l"(src)); \
            uint32_t da2 = (uint32_t)__cvta_generic_to_shared(&sDA[buf_][tid]);     \
            const float* src2 = dAb + (size_t)(t0_ + tid) * CNH;                    \
            asm volatile("cp.async.ca.shared.global [%0], [%1], 4;" :: "r"(da2), "l"(src2)); \
        }                                                                           \
        asm volatile("cp.async.commit_group;");                                     \
    }

    SCAN_ISSUE(0);

    for (int c = 0; c < SNCH; c++) {
        asm volatile("cp.async.wait_group 0;");
        __syncthreads();
        if (c + 1 < SNCH) SCAN_ISSUE(c + 1);
        const int buf = c & 1;
        const int t0 = c * SCHUNK;
#pragma unroll 6
        for (int tt = 0; tt < SCHUNK; tt++) {
            const unsigned long long a2  = pack2(sDA[buf][tt]);
            const unsigned long long sc2 = pack2(sDT[buf][tt] * sX[buf][tt][p_local]);
            const float* base = &sBC[buf][tt][0];
            unsigned long long accA = 0ull, accB = 0ull;
#pragma unroll
            for (int q = 0; q < 4; q++) {
                ulonglong2 bq = *reinterpret_cast<const ulonglong2*>(base + gB + 4 * q);
                ulonglong2 cq = *reinterpret_cast<const ulonglong2*>(base + gC + 4 * q);
                s2[2*q]   = fma_x2(a2, s2[2*q],   mul_x2(sc2, bq.x));
                s2[2*q+1] = fma_x2(a2, s2[2*q+1], mul_x2(sc2, bq.y));
                accA = fma_x2(s2[2*q],   cq.x, accA);
                accB = fma_x2(s2[2*q+1], cq.y, accB);
            }
            float acc = unpack_sum(add_x2(accA, accB));
            acc += __shfl_xor_sync(0xffffffffu, acc, 1);
            acc += __shfl_xor_sync(0xffffffffu, acc, 2);
            acc += __shfl_xor_sync(0xffffffffu, acc, 4);
            if (noct == 0) yb[(size_t)(t0 + tt) * CDIN + p_local] = acc;
        }
    }
#undef SCAN_ISSUE
}

// ---------------- gate+norm: warp per token ----------------
__global__ void gate_norm_kernel(const float* __restrict__ y, const float* __restrict__ xc,
                                 const float* __restrict__ proj, const float* __restrict__ Dv,
                                 const float* __restrict__ gw, float* __restrict__ out)
{
    int token = blockIdx.x * 8 + (threadIdx.x >> 5);
    int lane = threadIdx.x & 31;
    const float4* yrow = reinterpret_cast<const float4*>(y + (size_t)token * CDIN);
    const float4* xrow = reinterpret_cast<const float4*>(xc + (size_t)token * CCONVD);
    const float4* zrow = reinterpret_cast<const float4*>(proj + (size_t)token * CPROJ);
    float4 ya = yrow[lane],      yb2 = yrow[lane + 32];
    float4 xa = xrow[lane],      xb  = xrow[lane + 32];
    float4 za = zrow[lane],      zb  = zrow[lane + 32];
    float Da = Dv[lane >> 4];
    float Db = Dv[2 + (lane >> 4)];

    float4 va, vb;
    va.x = (ya.x + Da * xa.x) * (za.x / (1.f + __expf(-za.x)));
    va.y = (ya.y + Da * xa.y) * (za.y / (1.f + __expf(-za.y)));
    va.z = (ya.z + Da * xa.z) * (za.z / (1.f + __expf(-za.z)));
    va.w = (ya.w + Da * xa.w) * (za.w / (1.f + __expf(-za.w)));
    vb.x = (yb2.x + Db * xb.x) * (zb.x / (1.f + __expf(-zb.x)));
    vb.y = (yb2.y + Db * xb.y) * (zb.y / (1.f + __expf(-zb.y)));
    vb.z = (yb2.z + Db * xb.z) * (zb.z / (1.f + __expf(-zb.z)));
    vb.w = (yb2.w + Db * xb.w) * (zb.w / (1.f + __expf(-zb.w)));

    float ss = va.x*va.x + va.y*va.y + va.z*va.z + va.w*va.w
             + vb.x*vb.x + vb.y*vb.y + vb.z*vb.z + vb.w*vb.w;
#pragma unroll
    for (int o = 16; o; o >>= 1) ss += __shfl_xor_sync(0xffffffffu, ss, o);
    float sc = rsqrtf(ss * (1.f / 256.f) + CEPS);

    float4 ga = reinterpret_cast<const float4*>(gw)[lane];
    float4 gb = reinterpret_cast<const float4*>(gw)[lane + 32];
    float4 oa = make_float4(va.x*sc*ga.x, va.y*sc*ga.y, va.z*sc*ga.z, va.w*sc*ga.w);
    float4 ob = make_float4(vb.x*sc*gb.x, vb.y*sc*gb.y, vb.z*sc*gb.z, vb.w*sc*gb.w);
    float4* orow = reinterpret_cast<float4*>(out + (size_t)token * CDIN);
    orow[lane] = oa;
    orow[lane + 32] = ob;
}

// ---------------- head: fnorm RMSNorm + fwd/bwd merge, warp per token ----------------
__global__ void fnorm_merge_kernel(const float* __restrict__ h, const float* __restrict__ w,
                                   float* __restrict__ m)
{
    int tok = blockIdx.x * 8 + (threadIdx.x >> 5);
    int lane = threadIdx.x & 31;
    int b = tok / CL, l = tok % CL;
    const float4* rf = reinterpret_cast<const float4*>(h + (size_t)tok * CHID);
    const float4* rb = reinterpret_cast<const float4*>(
        h + (size_t)((CB0 + b) * CL + (CL - 1 - l)) * CHID);
    float4 a = rf[lane], c = rb[lane];
    float sa = a.x*a.x + a.y*a.y + a.z*a.z + a.w*a.w;
    float sb = c.x*c.x + c.y*c.y + c.z*c.z + c.w*c.w;
#pragma unroll
    for (int o = 16; o; o >>= 1) {
        sa += __shfl_xor_sync(0xffffffffu, sa, o);
        sb += __shfl_xor_sync(0xffffffffu, sb, o);
    }
    float ka = rsqrtf(sa * (1.f / 128.f) + CEPS);
    float kb = rsqrtf(sb * (1.f / 128.f) + CEPS);
    float4 wv = reinterpret_cast<const float4*>(w)[lane];
    float4 o4 = make_float4(0.5f * (a.x * ka + c.x * kb) * wv.x,
                            0.5f * (a.y * ka + c.y * kb) * wv.y,
                            0.5f * (a.z * ka + c.z * kb) * wv.z,
                            0.5f * (a.w * ka + c.w * kb) * wv.w);
    reinterpret_cast<float4*>(m + (size_t)tok * CHID)[lane] = o4;
}

// ---------------- launcher ----------------
extern "C" void kernel_launch(void* const* d_in, const int* in_sizes, int n_in,
                              void* d_out, int out_size)
{
    const float* x        = (const float*)d_in[0];
    const float* patch_w  = (const float*)d_in[1];
    const float* patch_b  = (const float*)d_in[2];
    const float* ln_w     = (const float*)d_in[3];
    const float* in_w     = (const float*)d_in[4];
    const float* in_b     = (const float*)d_in[5];
    const float* conv_w   = (const float*)d_in[6];
    const float* conv_b   = (const float*)d_in[7];
    const float* dt_bias  = (const float*)d_in[8];
    const float* A_log    = (const float*)d_in[9];
    const float* Dw       = (const float*)d_in[10];
    const float* gnorm_w  = (const float*)d_in[11];
    const float* out_w    = (const float*)d_in[12];
    const float* out_b    = (const float*)d_in[13];
    const float* fnorm_w  = (const float*)d_in[14];
    const float* r1_w     = (const float*)d_in[15];
    const float* r1_b     = (const float*)d_in[16];
    const float* r2_w     = (const float*)d_in[17];
    const float* r2_b     = (const float*)d_in[18];

    float *h_, *u_, *proj_, *xc_, *dt_, *dA_, *y_, *g_, *m_;
    cudaGetSymbolAddress((void**)&h_,    g_h);
    cudaGetSymbolAddress((void**)&u_,    g_u);
    cudaGetSymbolAddress((void**)&proj_, g_proj);
    cudaGetSymbolAddress((void**)&xc_,   g_xc);
    cudaGetSymbolAddress((void**)&dt_,   g_dt);
    cudaGetSymbolAddress((void**)&dA_,   g_dA);
    cudaGetSymbolAddress((void**)&y_,    g_y);
    cudaGetSymbolAddress((void**)&g_,    g_g);
    cudaGetSymbolAddress((void**)&m_,    g_m);

    // Idempotent dynamic-SMEM attribute (no static guards).
    cudaFuncSetAttribute(gemm_tc<0>, cudaFuncAttributeMaxDynamicSharedMemorySize, GSMEM_B);
    cudaFuncSetAttribute(gemm_tc<1>, cudaFuncAttributeMaxDynamicSharedMemorySize, GSMEM_B);
    cudaFuncSetAttribute(gemm_tc<2>, cudaFuncAttributeMaxDynamicSharedMemorySize, GSMEM_B);
    cudaFuncSetAttribute(gemm_tc<3>, cudaFuncAttributeMaxDynamicSharedMemorySize, GSMEM_B);
    cudaFuncSetAttribute(gemm_tc<4>, cudaFuncAttributeMaxDynamicSharedMemorySize, GSMEM_B);

    // 1. patch embedding (gather fused into GEMM A-load)
    gemm_tc<3><<<dim3(2, 96), 256, GSMEM_B>>>(x, patch_w, patch_b, nullptr, y_,
                                              M_FWD, 127, CPATCH);
    build_h<<<(CB0 * CL * CHID + 255) / 256, 256>>>(y_, h_);

    // 2. mixer layers
    for (int layer = 0; layer < CNL; layer++) {
        rmsnorm_kernel<<<M_ALL / 8, 256>>>(h_, ln_w + layer * CHID, u_, M_ALL);
        gemm_tc<0><<<dim3(13, 192), 256, GSMEM_B>>>(u_, in_w + (size_t)layer * CPROJ * CHID,
                                                    in_b + layer * CPROJ, nullptr, proj_,
                                                    M_ALL, CPROJ, CHID);
        conv_kernel<<<(CBZ * 255 * 128 + 255) / 256, 256>>>(
            proj_, conv_w + (size_t)layer * CCONVD * 4, conv_b + layer * CCONVD, xc_);
        dtprep_kernel<<<(CBZ * CL * CNH + 255) / 256, 256>>>(
            proj_, dt_bias + layer * CNH, A_log + layer * CNH, dt_, dA_);
        scan_kernel<<<dim3(2, CNH, CBZ), 256>>>(xc_, dt_, dA_, y_);
        gate_norm_kernel<<<M_ALL / 8, 256>>>(y_, xc_, proj_, Dw + layer * CNH,
                                             gnorm_w + layer * CDIN, g_);
        gemm_tc<1><<<dim3(2, 192), 256, GSMEM_B>>>(g_, out_w + (size_t)layer * CHID * CDIN,
                                                   out_b + layer * CHID, h_, h_,
                                                   M_ALL, CHID, CDIN);
    }

    // 3. head: fused fnorm+merge, r1 (GELU), r2 with unpatchify scatter epilogue
    fnorm_merge_kernel<<<M_FWD / 8, 256>>>(h_, fnorm_w, m_);
    gemm_tc<2><<<dim3(2, 96), 256, GSMEM_B>>>(m_, r1_w, r1_b, nullptr, u_, M_FWD, CHID, CHID);
    gemm_tc<4><<<dim3(8, 96), 256, GSMEM_B>>>(u_, r2_w, r2_b, nullptr, (float*)d_out,
                                              M_FWD, CPATCH, CHID);
}